// round 15
// baseline (speedup 1.0000x reference)
#include <cuda_runtime.h>
#include <math.h>
#include <stdint.h>

#define HASH_SIZE  (1u << 19)
#define HASH_MASK  (HASH_SIZE - 1u)
#define NT 128
#define NBINS (1 << 18)     // 64^3 Morton bins
#define MAXPTS (1 << 20)

typedef unsigned long long ull;

struct LParams {
    float rm1[16];
    int   R[16];
    int   dense[16];
};

// ---- static scratch (no allocations allowed) ----
__device__ int g_bins[NBINS];
__device__ int g_cnt[NBINS];
__device__ int g_binStart[NBINS];
__device__ int g_partials[256];
__device__ int g_perm[MAXPTS];

__device__ __forceinline__ void fma2(ull &acc, ull a, ull b) {
    asm("fma.rn.f32x2 %0, %1, %2, %0;" : "+l"(acc) : "l"(a), "l"(b));
}
__device__ __forceinline__ ull pack2(float x, float y) {
    ull r; asm("mov.b64 %0, {%1, %2};" : "=l"(r) : "f"(x), "f"(y)); return r;
}
__device__ __forceinline__ float2 unpack2(ull v) {
    float2 r; asm("mov.b64 {%0, %1}, %2;" : "=f"(r.x), "=f"(r.y) : "l"(v)); return r;
}

// fast softplus100: MUFU-based. Exact in linear region (z>20); abs err ~1e-8 otherwise.
__device__ __forceinline__ float sp100(float v) {
    float z = v * 100.0f;
    float s = 0.01f * __logf(1.0f + __expf(z));
    return (z > 20.0f) ? v : s;
}

// ---------------- sort pipeline ----------------
__device__ __forceinline__ uint32_t part3(uint32_t x) {
    x &= 0x3Fu;
    x = (x | (x << 16)) & 0x030000FFu;
    x = (x | (x << 8))  & 0x0300F00Fu;
    x = (x | (x << 4))  & 0x030C30C3u;
    x = (x | (x << 2))  & 0x09249249u;
    return x;
}
__device__ __forceinline__ uint32_t morton_key(const float* __restrict__ x, int i) {
    float px = x[3*i], py = x[3*i+1], pz = x[3*i+2];
    int kx = min(max((int)(px * 64.0f), 0), 63);
    int ky = min(max((int)(py * 64.0f), 0), 63);
    int kz = min(max((int)(pz * 64.0f), 0), 63);
    return part3(kx) | (part3(ky) << 1) | (part3(kz) << 2);
}

// 4 points per thread: 4 independent atomic chains overlap latency.
__global__ void k_hist(const float* __restrict__ x, int npts) {
    int base = (blockIdx.x * blockDim.x + threadIdx.x) * 4;
#pragma unroll
    for (int j = 0; j < 4; j++) {
        int i = base + j;
        if (i < npts) {
            uint32_t key = morton_key(x, i);
            atomicAdd(&g_bins[key], 1);
        }
    }
}

// shuffle-based block scan: 2 barriers instead of 20
__global__ void k_scan1() {            // 256 blocks x 1024
    __shared__ int wsum[32];
    int t = threadIdx.x;
    int g = blockIdx.x * 1024 + t;
    int lane = t & 31, w = t >> 5;
    int v = g_bins[g];
    int incl = v;
#pragma unroll
    for (int d = 1; d < 32; d <<= 1) {
        int a = __shfl_up_sync(0xffffffffu, incl, d);
        if (lane >= d) incl += a;
    }
    if (lane == 31) wsum[w] = incl;
    __syncthreads();
    if (w == 0) {
        int s = wsum[lane];
#pragma unroll
        for (int d = 1; d < 32; d <<= 1) {
            int a = __shfl_up_sync(0xffffffffu, s, d);
            if (lane >= d) s += a;
        }
        wsum[lane] = s;
    }
    __syncthreads();
    int wpre = (w == 0) ? 0 : wsum[w-1];
    int total_incl = incl + wpre;
    g_binStart[g] = total_incl - v;
    if (t == 1023) g_partials[blockIdx.x] = total_incl;
}

__global__ void k_scan2() {            // 1 block x 256
    __shared__ int wsum[8];
    int t = threadIdx.x;
    int lane = t & 31, w = t >> 5;
    int v = g_partials[t];
    int incl = v;
#pragma unroll
    for (int d = 1; d < 32; d <<= 1) {
        int a = __shfl_up_sync(0xffffffffu, incl, d);
        if (lane >= d) incl += a;
    }
    if (lane == 31) wsum[w] = incl;
    __syncthreads();
    if (w == 0 && lane < 8) {
        int s = wsum[lane];
#pragma unroll
        for (int d = 1; d < 8; d <<= 1) {
            int a = __shfl_up_sync(0x000000ffu, s, d);
            if (lane >= d) s += a;
        }
        wsum[lane] = s;
    }
    __syncthreads();
    int wpre = (w == 0) ? 0 : wsum[w-1];
    g_partials[t] = incl + wpre - v;
}

// scan3 folded in: global bin start = binStart[k] + partials[k>>10].
// 4 points per thread; key recomputed from x (identical float math -> same key).
__global__ void k_scatter(const float* __restrict__ x, int npts) {
    int base = (blockIdx.x * blockDim.x + threadIdx.x) * 4;
#pragma unroll
    for (int j = 0; j < 4; j++) {
        int i = base + j;
        if (i < npts) {
            uint32_t k = morton_key(x, i);
            int pos = g_binStart[k] + g_partials[k >> 10] + atomicAdd(&g_cnt[k], 1);
            g_perm[pos] = i;
        }
    }
}

// ---------------- fused main kernel ----------------
__device__ __forceinline__ void addin2(ull accS[16], ull accO[16],
                                       float vS, float vO, const float* col32) {
    const ulonglong2* c = (const ulonglong2*)col32;
    ull a = pack2(vS, vS);
    ull b = pack2(vO, vO);
#pragma unroll
    for (int q = 0; q < 8; q++) {
        ulonglong2 w = c[q];
        fma2(accS[2*q+0], a, w.x);
        fma2(accS[2*q+1], a, w.y);
        fma2(accO[2*q+0], b, w.x);
        fma2(accO[2*q+1], b, w.y);
    }
}

__global__ void __launch_bounds__(NT, 4) nerf_fused(
    const float* __restrict__ xin,
    const float* __restrict__ tables,
    const float* __restrict__ W0, const float* __restrict__ b0,
    const float* __restrict__ W1, const float* __restrict__ b1,
    const float* __restrict__ W2, const float* __restrict__ b2,
    float* __restrict__ out, int npts, LParams lp)
{
    __shared__ __align__(16) float sW0T[71*72];   // col i: even half at +0, odd at +36; reused as out stage
    __shared__ __align__(16) float sW1p[64*72];
    __shared__ __align__(16) float sW2T[64*20];
    __shared__ float sb0[64];
    __shared__ float sb1[64];
    __shared__ float sb2p[20];
    __shared__ int   sRow[NT];

    const int tid = threadIdx.x;
    for (int k = tid; k < 71*64; k += NT) {
        int i = k >> 6, j = k & 63;
        int jo = (j < 32) ? j : (j + 4);           // odd half at +36
        sW0T[i*72 + jo] = W0[j*71 + i];
    }
    for (int k = tid; k < 64*64; k += NT) {
        int r = k >> 6, j = k & 63;
        int jo = (j < 32) ? j : (j + 4);
        sW1p[r*72 + jo] = W1[k];
    }
    for (int k = tid; k < 64*20; k += NT) {
        int j = k / 20, o = k % 20;
        sW2T[k] = (o < 17) ? W2[o*64 + j] : 0.0f;
    }
    if (tid < 64) { sb0[tid] = b0[tid]; sb1[tid] = b1[tid]; }
    if (tid < 20) sb2p[tid] = (tid < 17) ? b2[tid] : 0.0f;
    __syncthreads();

    const int gid = blockIdx.x * NT + tid;
    const bool valid = (gid < npts);
    const int n = valid ? g_perm[gid] : g_perm[0];
    const int half = tid & 1;
    const float* colHalf = sW0T + half * 36;

    const float px = xin[n*3+0], py = xin[n*3+1], pz = xin[n*3+2];

    ull accS[16], accO[16];
    const int hb = half * 32;
#pragma unroll
    for (int q = 0; q < 16; q++) {
        ull bv = pack2(sb0[hb + 2*q], sb0[hb + 2*q + 1]);
        accS[q] = bv;
        accO[q] = bv;
    }

    // inputs 0..2
    {
        float vO;
        vO = __shfl_xor_sync(0xffffffffu, px, 1); addin2(accS, accO, px, vO, colHalf + 0*72);
        vO = __shfl_xor_sync(0xffffffffu, py, 1); addin2(accS, accO, py, vO, colHalf + 1*72);
        vO = __shfl_xor_sync(0xffffffffu, pz, 1); addin2(accS, accO, pz, vO, colHalf + 2*72);
    }

    // inputs 3..38: positional embedding (fast MUFU trig; angle <= 32 rad)
#pragma unroll 1
    for (int m = 0; m < 6; m++) {
        float f = (float)(1 << m);
        float ax = px * f, ay = py * f, az = pz * f;
        float sx = __sinf(ax), cx = __cosf(ax);
        float sy = __sinf(ay), cy = __cosf(ay);
        float sz = __sinf(az), cz = __cosf(az);
        const float* base = colHalf + (3 + 6*m) * 72;
        float vO;
        vO = __shfl_xor_sync(0xffffffffu, sx, 1); addin2(accS, accO, sx, vO, base + 0*72);
        vO = __shfl_xor_sync(0xffffffffu, sy, 1); addin2(accS, accO, sy, vO, base + 1*72);
        vO = __shfl_xor_sync(0xffffffffu, sz, 1); addin2(accS, accO, sz, vO, base + 2*72);
        vO = __shfl_xor_sync(0xffffffffu, cx, 1); addin2(accS, accO, cx, vO, base + 3*72);
        vO = __shfl_xor_sync(0xffffffffu, cy, 1); addin2(accS, accO, cy, vO, base + 4*72);
        vO = __shfl_xor_sync(0xffffffffu, cz, 1); addin2(accS, accO, cz, vO, base + 5*72);
    }

    // inputs 39..70: hash-grid features
#pragma unroll 1
    for (int l = 0; l < 16; l++) {
        const float rm1 = lp.rm1[l];
        const int   R   = lp.R[l];
        float fx = px * rm1, fy = py * rm1, fz = pz * rm1;
        float p0x = floorf(fx), p0y = floorf(fy), p0z = floorf(fz);
        float wx = fx - p0x, wy = fy - p0y, wz = fz - p0z;
        int ix = (int)p0x, iy = (int)p0y, iz = (int)p0z;
        int x0 = max(min(ix,     R-1), 0), x1 = max(min(ix + 1, R-1), 0);
        int y0 = max(min(iy,     R-1), 0), y1 = max(min(iy + 1, R-1), 0);
        int z0 = max(min(iz,     R-1), 0), z1 = max(min(iz + 1, R-1), 0);

        uint32_t i000, i001, i010, i011, i100, i101, i110, i111;
        if (lp.dense[l]) {
            int R2 = R * R;
            int az0 = z0 * R2, az1 = z1 * R2;
            int ay0 = y0 * R,  ay1 = y1 * R;
            i000 = (uint32_t)(x0 + ay0 + az0);
            i001 = (uint32_t)(x0 + ay0 + az1);
            i010 = (uint32_t)(x0 + ay1 + az0);
            i011 = (uint32_t)(x0 + ay1 + az1);
            i100 = (uint32_t)(x1 + ay0 + az0);
            i101 = (uint32_t)(x1 + ay0 + az1);
            i110 = (uint32_t)(x1 + ay1 + az0);
            i111 = (uint32_t)(x1 + ay1 + az1);
        } else {
            // PRIME0 == 1: h = x ^ (y*P1) ^ (z*P2). Precompute the 4 y/z combos.
            uint32_t hy0 = (uint32_t)y0 * 2654435761u, hy1 = (uint32_t)y1 * 2654435761u;
            uint32_t hz0 = (uint32_t)z0 * 805459861u,  hz1 = (uint32_t)z1 * 805459861u;
            uint32_t a00 = hy0 ^ hz0, a01 = hy0 ^ hz1;
            uint32_t a10 = hy1 ^ hz0, a11 = hy1 ^ hz1;
            uint32_t ux0 = (uint32_t)x0, ux1 = (uint32_t)x1;
            i000 = (ux0 ^ a00) & HASH_MASK;
            i001 = (ux0 ^ a01) & HASH_MASK;
            i010 = (ux0 ^ a10) & HASH_MASK;
            i011 = (ux0 ^ a11) & HASH_MASK;
            i100 = (ux1 ^ a00) & HASH_MASK;
            i101 = (ux1 ^ a01) & HASH_MASK;
            i110 = (ux1 ^ a10) & HASH_MASK;
            i111 = (ux1 ^ a11) & HASH_MASK;
        }

        const float2* tb = (const float2*)tables + (size_t)l * HASH_SIZE;
        float2 t000 = __ldg(tb + i000);
        float2 t001 = __ldg(tb + i001);
        float2 t010 = __ldg(tb + i010);
        float2 t011 = __ldg(tb + i011);
        float2 t100 = __ldg(tb + i100);
        float2 t101 = __ldg(tb + i101);
        float2 t110 = __ldg(tb + i110);
        float2 t111 = __ldg(tb + i111);

        float ux = 1.0f - wx, uy = 1.0f - wy, uz = 1.0f - wz;
        float w000 = ux*uy*uz, w001 = ux*uy*wz, w010 = ux*wy*uz, w011 = ux*wy*wz;
        float w100 = wx*uy*uz, w101 = wx*uy*wz, w110 = wx*wy*uz, w111 = wx*wy*wz;

        float f0 = w000*t000.x + w001*t001.x + w010*t010.x + w011*t011.x
                 + w100*t100.x + w101*t101.x + w110*t110.x + w111*t111.x;
        float f1 = w000*t000.y + w001*t001.y + w010*t010.y + w011*t011.y
                 + w100*t100.y + w101*t101.y + w110*t110.y + w111*t111.y;

        const float* colp = colHalf + (39 + 2*l) * 72;
        float f0O = __shfl_xor_sync(0xffffffffu, f0, 1);
        float f1O = __shfl_xor_sync(0xffffffffu, f1, 1);
        addin2(accS, accO, f0, f0O, colp);
        addin2(accS, accO, f1, f1O, colp + 72);
    }

    // activation
#pragma unroll
    for (int q = 0; q < 16; q++) {
        float2 a = unpack2(accS[q]);
        accS[q] = pack2(sp100(a.x), sp100(a.y));
        float2 b = unpack2(accO[q]);
        accO[q] = pack2(sp100(b.x), sp100(b.y));
    }

    // layers 1+2 fused
    ull o17[9];
#pragma unroll
    for (int t = 0; t < 9; t++) o17[t] = pack2(sb2p[2*t], sb2p[2*t+1]);

#pragma unroll 2
    for (int r = 0; r < 64; r++) {
        const ulonglong2* wr = (const ulonglong2*)(sW1p + r*72 + half*36);
        ull sS = 0, sO = 0;
#pragma unroll
        for (int q = 0; q < 8; q++) {
            ulonglong2 w = wr[q];
            fma2(sS, w.x, accS[2*q+0]);
            fma2(sS, w.y, accS[2*q+1]);
            fma2(sO, w.x, accO[2*q+0]);
            fma2(sO, w.y, accO[2*q+1]);
        }
        float2 fs = unpack2(sS);
        float2 fo = unpack2(sO);
        float pS = fs.x + fs.y;
        float pO = fo.x + fo.y;
        float cross = __shfl_xor_sync(0xffffffffu, pO, 1);
        float v = sp100(pS + cross + sb1[r]);
        ull vv = pack2(v, v);
        const ulonglong2* w2q = (const ulonglong2*)(sW2T + r*20);
#pragma unroll
        for (int q = 0; q < 4; q++) {
            ulonglong2 w = w2q[q];
            fma2(o17[2*q+0], vv, w.x);
            fma2(o17[2*q+1], vv, w.y);
        }
        fma2(o17[8], vv, *(const ull*)(sW2T + r*20 + 16));
    }

    // ---- stage outputs to smem (reuse sW0T), then warp-cooperative scattered row writes ----
    __syncthreads();                   // everyone done reading sW0T
    float* stage = sW0T;               // 128*17 = 2176 floats < 71*72
    sRow[tid] = valid ? n : -1;
#pragma unroll
    for (int t = 0; t < 8; t++) {
        float2 v = unpack2(o17[t]);
        stage[tid*17 + 2*t + 0] = v.x;
        stage[tid*17 + 2*t + 1] = v.y;
    }
    stage[tid*17 + 16] = unpack2(o17[8]).x;
    __syncthreads();

    const int wid = tid >> 5, lane = tid & 31;
    if (lane < 17) {
#pragma unroll 1
        for (int r = wid*32; r < wid*32 + 32; r++) {
            int rowIdx = sRow[r];
            if (rowIdx >= 0) out[(size_t)rowIdx*17 + lane] = stage[r*17 + lane];
        }
    }
}

extern "C" void kernel_launch(void* const* d_in, const int* in_sizes, int n_in,
                              void* d_out, int out_size)
{
    const float* x  = (const float*)d_in[0];
    const float* tb = (const float*)d_in[1];
    const float* W0 = (const float*)d_in[2];
    const float* b0 = (const float*)d_in[3];
    const float* W1 = (const float*)d_in[4];
    const float* b1 = (const float*)d_in[5];
    const float* W2 = (const float*)d_in[6];
    const float* b2 = (const float*)d_in[7];
    float* out = (float*)d_out;

    int npts = in_sizes[0] / 3;

    LParams lp;
    double scale = exp2(log2(2048.0 / 16.0) / 15.0);
    for (int l = 0; l < 16; l++) {
        int R = (int)ceil(16.0 * pow(scale, (double)l));
        lp.R[l]     = R;
        lp.rm1[l]   = (float)(R - 1);
        lp.dense[l] = ((long long)R * R * R <= (long long)HASH_SIZE) ? 1 : 0;
    }

    // ---- sort pipeline ----
    void* bins_ptr = nullptr;
    void* cnt_ptr  = nullptr;
    cudaGetSymbolAddress(&bins_ptr, g_bins);
    cudaGetSymbolAddress(&cnt_ptr,  g_cnt);
    cudaMemsetAsync(bins_ptr, 0, NBINS * sizeof(int));
    cudaMemsetAsync(cnt_ptr,  0, NBINS * sizeof(int));
    int qthreads = (npts + 3) / 4;
    k_hist<<<(qthreads + 255)/256, 256>>>(x, npts);
    k_scan1<<<NBINS/1024, 1024>>>();
    k_scan2<<<1, 256>>>();
    k_scatter<<<(qthreads + 255)/256, 256>>>(x, npts);

    // ---- fused main ----
    int blocks = (npts + NT - 1) / NT;
    nerf_fused<<<blocks, NT>>>(x, tb, W0, b0, W1, b1, W2, b2, out, npts, lp);
}

// round 16
// speedup vs baseline: 1.5978x; 1.5978x over previous
#include <cuda_runtime.h>
#include <math.h>
#include <stdint.h>

#define HASH_SIZE  (1u << 19)
#define HASH_MASK  (HASH_SIZE - 1u)
#define NT 128
#define NBINS (1 << 18)     // 64^3 Morton bins
#define MAXPTS (1 << 20)

typedef unsigned long long ull;

struct LParams {
    float rm1[16];
    int   R[16];
    int   dense[16];
};

// ---- static scratch (no allocations allowed) ----
__device__ int g_bins[NBINS];
__device__ int g_cnt[NBINS];
__device__ int g_binStart[NBINS];
__device__ int g_partials[256];
__device__ int g_keys[MAXPTS];
__device__ int g_perm[MAXPTS];

__device__ __forceinline__ void fma2(ull &acc, ull a, ull b) {
    asm("fma.rn.f32x2 %0, %1, %2, %0;" : "+l"(acc) : "l"(a), "l"(b));
}
__device__ __forceinline__ ull pack2(float x, float y) {
    ull r; asm("mov.b64 %0, {%1, %2};" : "=l"(r) : "f"(x), "f"(y)); return r;
}
__device__ __forceinline__ float2 unpack2(ull v) {
    float2 r; asm("mov.b64 {%0, %1}, %2;" : "=f"(r.x), "=f"(r.y) : "l"(v)); return r;
}

// fast softplus100: MUFU-based. Exact in linear region (z>20); abs err ~1e-8 otherwise.
__device__ __forceinline__ float sp100(float v) {
    float z = v * 100.0f;
    float s = 0.01f * __logf(1.0f + __expf(z));
    return (z > 20.0f) ? v : s;
}

// ---------------- sort pipeline ----------------
__device__ __forceinline__ uint32_t part3(uint32_t x) {
    x &= 0x3Fu;
    x = (x | (x << 16)) & 0x030000FFu;
    x = (x | (x << 8))  & 0x0300F00Fu;
    x = (x | (x << 4))  & 0x030C30C3u;
    x = (x | (x << 2))  & 0x09249249u;
    return x;
}
__global__ void k_zero() {
    int i = blockIdx.x * blockDim.x + threadIdx.x;
    if (i < NBINS) { g_bins[i] = 0; g_cnt[i] = 0; }
}
__global__ void k_hist(const float* __restrict__ x, int npts) {
    int i = blockIdx.x * blockDim.x + threadIdx.x;
    if (i >= npts) return;
    float px = x[3*i], py = x[3*i+1], pz = x[3*i+2];
    int kx = min(max((int)(px * 64.0f), 0), 63);
    int ky = min(max((int)(py * 64.0f), 0), 63);
    int kz = min(max((int)(pz * 64.0f), 0), 63);
    uint32_t key = part3(kx) | (part3(ky) << 1) | (part3(kz) << 2);
    g_keys[i] = (int)key;
    atomicAdd(&g_bins[key], 1);
}
__global__ void k_scan1() {            // 256 blocks x 1024: per-block exclusive scan
    __shared__ int s[1024];
    int t = threadIdx.x;
    int g = blockIdx.x * 1024 + t;
    int v = g_bins[g];
    s[t] = v; __syncthreads();
#pragma unroll
    for (int d = 1; d < 1024; d <<= 1) {
        int add = (t >= d) ? s[t-d] : 0;
        __syncthreads();
        s[t] += add;
        __syncthreads();
    }
    g_binStart[g] = s[t] - v;
    if (t == 1023) g_partials[blockIdx.x] = s[t];
}
__global__ void k_scan2() {            // 1 block x 256: exclusive scan of block totals
    __shared__ int s[256];
    int t = threadIdx.x;
    int v = g_partials[t];
    s[t] = v; __syncthreads();
#pragma unroll
    for (int d = 1; d < 256; d <<= 1) {
        int add = (t >= d) ? s[t-d] : 0;
        __syncthreads();
        s[t] += add;
        __syncthreads();
    }
    g_partials[t] = s[t] - v;
}
// scan3 folded in: global bin start = binStart[k] + partials[k>>10]
__global__ void k_scatter(int npts) {
    int i = blockIdx.x * blockDim.x + threadIdx.x;
    if (i >= npts) return;
    int k = g_keys[i];
    int pos = g_binStart[k] + g_partials[k >> 10] + atomicAdd(&g_cnt[k], 1);
    g_perm[pos] = i;
}

// ---------------- fused main kernel ----------------
__device__ __forceinline__ void addin2(ull accS[16], ull accO[16],
                                       float vS, float vO, const float* col32) {
    const ulonglong2* c = (const ulonglong2*)col32;
    ull a = pack2(vS, vS);
    ull b = pack2(vO, vO);
#pragma unroll
    for (int q = 0; q < 8; q++) {
        ulonglong2 w = c[q];
        fma2(accS[2*q+0], a, w.x);
        fma2(accS[2*q+1], a, w.y);
        fma2(accO[2*q+0], b, w.x);
        fma2(accO[2*q+1], b, w.y);
    }
}

__global__ void __launch_bounds__(NT, 4) nerf_fused(
    const float* __restrict__ xin,
    const float* __restrict__ tables,
    const float* __restrict__ W0, const float* __restrict__ b0,
    const float* __restrict__ W1, const float* __restrict__ b1,
    const float* __restrict__ W2, const float* __restrict__ b2,
    float* __restrict__ out, int npts, LParams lp)
{
    __shared__ __align__(16) float sW0T[71*72];   // col i: even half at +0, odd at +36; reused as out stage
    __shared__ __align__(16) float sW1p[64*72];
    __shared__ __align__(16) float sW2T[64*20];
    __shared__ float sb0[64];
    __shared__ float sb1[64];
    __shared__ float sb2p[20];
    __shared__ int   sRow[NT];

    const int tid = threadIdx.x;
    for (int k = tid; k < 71*64; k += NT) {
        int i = k >> 6, j = k & 63;
        int jo = (j < 32) ? j : (j + 4);           // odd half at +36
        sW0T[i*72 + jo] = W0[j*71 + i];
    }
    for (int k = tid; k < 64*64; k += NT) {
        int r = k >> 6, j = k & 63;
        int jo = (j < 32) ? j : (j + 4);
        sW1p[r*72 + jo] = W1[k];
    }
    for (int k = tid; k < 64*20; k += NT) {
        int j = k / 20, o = k % 20;
        sW2T[k] = (o < 17) ? W2[o*64 + j] : 0.0f;
    }
    if (tid < 64) { sb0[tid] = b0[tid]; sb1[tid] = b1[tid]; }
    if (tid < 20) sb2p[tid] = (tid < 17) ? b2[tid] : 0.0f;
    __syncthreads();

    const int gid = blockIdx.x * NT + tid;
    const bool valid = (gid < npts);
    const int n = valid ? g_perm[gid] : g_perm[0];
    const int half = tid & 1;
    const float* colHalf = sW0T + half * 36;

    const float px = xin[n*3+0], py = xin[n*3+1], pz = xin[n*3+2];

    ull accS[16], accO[16];
    const int hb = half * 32;
#pragma unroll
    for (int q = 0; q < 16; q++) {
        ull bv = pack2(sb0[hb + 2*q], sb0[hb + 2*q + 1]);
        accS[q] = bv;
        accO[q] = bv;
    }

    // inputs 0..2
    {
        float vO;
        vO = __shfl_xor_sync(0xffffffffu, px, 1); addin2(accS, accO, px, vO, colHalf + 0*72);
        vO = __shfl_xor_sync(0xffffffffu, py, 1); addin2(accS, accO, py, vO, colHalf + 1*72);
        vO = __shfl_xor_sync(0xffffffffu, pz, 1); addin2(accS, accO, pz, vO, colHalf + 2*72);
    }

    // inputs 3..38: positional embedding (fast MUFU trig; angle <= 32 rad)
#pragma unroll 1
    for (int m = 0; m < 6; m++) {
        float f = (float)(1 << m);
        float ax = px * f, ay = py * f, az = pz * f;
        float sx = __sinf(ax), cx = __cosf(ax);
        float sy = __sinf(ay), cy = __cosf(ay);
        float sz = __sinf(az), cz = __cosf(az);
        const float* base = colHalf + (3 + 6*m) * 72;
        float vO;
        vO = __shfl_xor_sync(0xffffffffu, sx, 1); addin2(accS, accO, sx, vO, base + 0*72);
        vO = __shfl_xor_sync(0xffffffffu, sy, 1); addin2(accS, accO, sy, vO, base + 1*72);
        vO = __shfl_xor_sync(0xffffffffu, sz, 1); addin2(accS, accO, sz, vO, base + 2*72);
        vO = __shfl_xor_sync(0xffffffffu, cx, 1); addin2(accS, accO, cx, vO, base + 3*72);
        vO = __shfl_xor_sync(0xffffffffu, cy, 1); addin2(accS, accO, cy, vO, base + 4*72);
        vO = __shfl_xor_sync(0xffffffffu, cz, 1); addin2(accS, accO, cz, vO, base + 5*72);
    }

    // inputs 39..70: hash-grid features
#pragma unroll 1
    for (int l = 0; l < 16; l++) {
        const float rm1 = lp.rm1[l];
        const int   R   = lp.R[l];
        float fx = px * rm1, fy = py * rm1, fz = pz * rm1;
        float p0x = floorf(fx), p0y = floorf(fy), p0z = floorf(fz);
        float wx = fx - p0x, wy = fy - p0y, wz = fz - p0z;
        int ix = (int)p0x, iy = (int)p0y, iz = (int)p0z;
        int x0 = max(min(ix,     R-1), 0), x1 = max(min(ix + 1, R-1), 0);
        int y0 = max(min(iy,     R-1), 0), y1 = max(min(iy + 1, R-1), 0);
        int z0 = max(min(iz,     R-1), 0), z1 = max(min(iz + 1, R-1), 0);

        uint32_t i000, i001, i010, i011, i100, i101, i110, i111;
        if (lp.dense[l]) {
            int R2 = R * R;
            int az0 = z0 * R2, az1 = z1 * R2;
            int ay0 = y0 * R,  ay1 = y1 * R;
            i000 = (uint32_t)(x0 + ay0 + az0);
            i001 = (uint32_t)(x0 + ay0 + az1);
            i010 = (uint32_t)(x0 + ay1 + az0);
            i011 = (uint32_t)(x0 + ay1 + az1);
            i100 = (uint32_t)(x1 + ay0 + az0);
            i101 = (uint32_t)(x1 + ay0 + az1);
            i110 = (uint32_t)(x1 + ay1 + az0);
            i111 = (uint32_t)(x1 + ay1 + az1);
        } else {
            // PRIME0 == 1: h = x ^ (y*P1) ^ (z*P2). Precompute the 4 y/z combos.
            uint32_t hy0 = (uint32_t)y0 * 2654435761u, hy1 = (uint32_t)y1 * 2654435761u;
            uint32_t hz0 = (uint32_t)z0 * 805459861u,  hz1 = (uint32_t)z1 * 805459861u;
            uint32_t a00 = hy0 ^ hz0, a01 = hy0 ^ hz1;
            uint32_t a10 = hy1 ^ hz0, a11 = hy1 ^ hz1;
            uint32_t ux0 = (uint32_t)x0, ux1 = (uint32_t)x1;
            i000 = (ux0 ^ a00) & HASH_MASK;
            i001 = (ux0 ^ a01) & HASH_MASK;
            i010 = (ux0 ^ a10) & HASH_MASK;
            i011 = (ux0 ^ a11) & HASH_MASK;
            i100 = (ux1 ^ a00) & HASH_MASK;
            i101 = (ux1 ^ a01) & HASH_MASK;
            i110 = (ux1 ^ a10) & HASH_MASK;
            i111 = (ux1 ^ a11) & HASH_MASK;
        }

        const float2* tb = (const float2*)tables + (size_t)l * HASH_SIZE;
        float2 t000 = __ldg(tb + i000);
        float2 t001 = __ldg(tb + i001);
        float2 t010 = __ldg(tb + i010);
        float2 t011 = __ldg(tb + i011);
        float2 t100 = __ldg(tb + i100);
        float2 t101 = __ldg(tb + i101);
        float2 t110 = __ldg(tb + i110);
        float2 t111 = __ldg(tb + i111);

        float ux = 1.0f - wx, uy = 1.0f - wy, uz = 1.0f - wz;
        float w000 = ux*uy*uz, w001 = ux*uy*wz, w010 = ux*wy*uz, w011 = ux*wy*wz;
        float w100 = wx*uy*uz, w101 = wx*uy*wz, w110 = wx*wy*uz, w111 = wx*wy*wz;

        float f0 = w000*t000.x + w001*t001.x + w010*t010.x + w011*t011.x
                 + w100*t100.x + w101*t101.x + w110*t110.x + w111*t111.x;
        float f1 = w000*t000.y + w001*t001.y + w010*t010.y + w011*t011.y
                 + w100*t100.y + w101*t101.y + w110*t110.y + w111*t111.y;

        const float* colp = colHalf + (39 + 2*l) * 72;
        float f0O = __shfl_xor_sync(0xffffffffu, f0, 1);
        float f1O = __shfl_xor_sync(0xffffffffu, f1, 1);
        addin2(accS, accO, f0, f0O, colp);
        addin2(accS, accO, f1, f1O, colp + 72);
    }

    // activation
#pragma unroll
    for (int q = 0; q < 16; q++) {
        float2 a = unpack2(accS[q]);
        accS[q] = pack2(sp100(a.x), sp100(a.y));
        float2 b = unpack2(accO[q]);
        accO[q] = pack2(sp100(b.x), sp100(b.y));
    }

    // layers 1+2 fused
    ull o17[9];
#pragma unroll
    for (int t = 0; t < 9; t++) o17[t] = pack2(sb2p[2*t], sb2p[2*t+1]);

#pragma unroll 2
    for (int r = 0; r < 64; r++) {
        const ulonglong2* wr = (const ulonglong2*)(sW1p + r*72 + half*36);
        ull sS = 0, sO = 0;
#pragma unroll
        for (int q = 0; q < 8; q++) {
            ulonglong2 w = wr[q];
            fma2(sS, w.x, accS[2*q+0]);
            fma2(sS, w.y, accS[2*q+1]);
            fma2(sO, w.x, accO[2*q+0]);
            fma2(sO, w.y, accO[2*q+1]);
        }
        float2 fs = unpack2(sS);
        float2 fo = unpack2(sO);
        float pS = fs.x + fs.y;
        float pO = fo.x + fo.y;
        float cross = __shfl_xor_sync(0xffffffffu, pO, 1);
        float v = sp100(pS + cross + sb1[r]);
        ull vv = pack2(v, v);
        const ulonglong2* w2q = (const ulonglong2*)(sW2T + r*20);
#pragma unroll
        for (int q = 0; q < 4; q++) {
            ulonglong2 w = w2q[q];
            fma2(o17[2*q+0], vv, w.x);
            fma2(o17[2*q+1], vv, w.y);
        }
        fma2(o17[8], vv, *(const ull*)(sW2T + r*20 + 16));
    }

    // ---- stage outputs to smem (reuse sW0T), then warp-cooperative scattered row writes ----
    __syncthreads();                   // everyone done reading sW0T
    float* stage = sW0T;               // 128*17 = 2176 floats < 71*72
    sRow[tid] = valid ? n : -1;
#pragma unroll
    for (int t = 0; t < 8; t++) {
        float2 v = unpack2(o17[t]);
        stage[tid*17 + 2*t + 0] = v.x;
        stage[tid*17 + 2*t + 1] = v.y;
    }
    stage[tid*17 + 16] = unpack2(o17[8]).x;
    __syncthreads();

    const int wid = tid >> 5, lane = tid & 31;
    if (lane < 17) {
#pragma unroll 1
        for (int r = wid*32; r < wid*32 + 32; r++) {
            int rowIdx = sRow[r];
            if (rowIdx >= 0) out[(size_t)rowIdx*17 + lane] = stage[r*17 + lane];
        }
    }
}

extern "C" void kernel_launch(void* const* d_in, const int* in_sizes, int n_in,
                              void* d_out, int out_size)
{
    const float* x  = (const float*)d_in[0];
    const float* tb = (const float*)d_in[1];
    const float* W0 = (const float*)d_in[2];
    const float* b0 = (const float*)d_in[3];
    const float* W1 = (const float*)d_in[4];
    const float* b1 = (const float*)d_in[5];
    const float* W2 = (const float*)d_in[6];
    const float* b2 = (const float*)d_in[7];
    float* out = (float*)d_out;

    int npts = in_sizes[0] / 3;

    LParams lp;
    double scale = exp2(log2(2048.0 / 16.0) / 15.0);
    for (int l = 0; l < 16; l++) {
        int R = (int)ceil(16.0 * pow(scale, (double)l));
        lp.R[l]     = R;
        lp.rm1[l]   = (float)(R - 1);
        lp.dense[l] = ((long long)R * R * R <= (long long)HASH_SIZE) ? 1 : 0;
    }

    // ---- sort pipeline ----
    k_zero<<<(NBINS + 255)/256, 256>>>();
    k_hist<<<(npts + 255)/256, 256>>>(x, npts);
    k_scan1<<<NBINS/1024, 1024>>>();
    k_scan2<<<1, 256>>>();
    k_scatter<<<(npts + 255)/256, 256>>>(npts);

    // ---- fused main ----
    int blocks = (npts + NT - 1) / NT;
    nerf_fused<<<blocks, NT>>>(x, tb, W0, b0, W1, b1, W2, b2, out, npts, lp);
}